// round 10
// baseline (speedup 1.0000x reference)
#include <cuda_runtime.h>
#include <cstdint>

#define BATCH 16
#define CIN   256
#define COUT  256
#define HH    64
#define WW    64
#define LAT   512
#define KTOT  2304

// ---------------- scratch (device globals; no allocation) ----------------
__device__ __align__(16) float g_s[BATCH * CIN];
__device__ __align__(16) float g_d[BATCH * COUT];
__device__ __align__(16) float g_wss[CIN * COUT];
// A panels, fragment-major: [b][cot][chunk(72)][ks(4)][wm(2)][mt(4)][lane(32)] float4
__device__ __align__(16) float g_wA[(size_t)BATCH * 2 * KTOT * 128];

__device__ __forceinline__ uint32_t tf32_rna(float v) {
    uint32_t u;
    asm("cvt.rna.tf32.f32 %0, %1;" : "=r"(u) : "f"(v));
    return u;
}

// ---------------- prep kernels ----------------
__global__ void fused1_kernel(const float* __restrict__ style,
                              const float* __restrict__ style_w,
                              const float* __restrict__ style_b,
                              const float* __restrict__ weight) {
    if (blockIdx.x < 16) {
        __shared__ float st[LAT];
        int b = blockIdx.x, tid = threadIdx.x;
        st[tid]       = style[b * LAT + tid];
        st[tid + 256] = style[b * LAT + tid + 256];
        __syncthreads();
        float acc = style_b[tid];
#pragma unroll 8
        for (int l = 0; l < LAT; l++) acc += st[l] * style_w[l * CIN + tid];
        g_s[b * CIN + tid] = acc;
    } else {
        int ci = blockIdx.x - 16, co = threadIdx.x;
        const float* wp = weight + co * (CIN * 9) + ci * 9;
        float s = 0.f;
#pragma unroll
        for (int t = 0; t < 9; t++) { float v = wp[t]; s += v * v; }
        g_wss[ci * COUT + co] = s;
    }
}

__global__ void d_kernel() {
    __shared__ float s2[CIN];
    int b = blockIdx.x, co = threadIdx.x;
    float sv = g_s[b * CIN + co];
    s2[co] = sv * sv;
    __syncthreads();
    float acc = 1e-8f;
#pragma unroll 8
    for (int ci = 0; ci < CIN; ci++) acc += g_wss[ci * COUT + co] * s2[ci];
    g_d[b * COUT + co] = rsqrtf(acc);
}

// Fragment-major modulated weights (validated layout, unchanged).
__global__ void wa_kernel(const float* __restrict__ weight) {
    int o = blockIdx.x * 256 + threadIdx.x;
    int lane = o & 31; int t = o >> 5;
    int mt = t & 3;  t >>= 2;
    int wm = t & 1;  t >>= 1;
    int ks = t & 3;  t >>= 2;
    int chunk = t % 72; t /= 72;
    int cot = t & 1; int b = t >> 1;
    int g = lane >> 2, tig = lane & 3;
    int kk  = ks * 8 + tig;
    int cig = chunk / 9, tap = chunk - 9 * cig;
    int ci  = cig * 32 + kk;
    int co  = cot * 128 + wm * 64 + mt * 16 + g;
    float s0 = g_s[b * CIN + ci],  s1 = g_s[b * CIN + ci + 4];
    float d0 = g_d[b * COUT + co], d1 = g_d[b * COUT + co + 8];
    float4 r;
    r.x = __uint_as_float(tf32_rna(weight[(co * CIN + ci) * 9 + tap]           * s0 * d0));
    r.y = __uint_as_float(tf32_rna(weight[((co + 8) * CIN + ci) * 9 + tap]     * s0 * d1));
    r.z = __uint_as_float(tf32_rna(weight[(co * CIN + ci + 4) * 9 + tap]       * s1 * d0));
    r.w = __uint_as_float(tf32_rna(weight[((co + 8) * CIN + ci + 4) * 9 + tap] * s1 * d1));
    ((float4*)g_wA)[o] = r;
}

// ---------------- main: 128x256 tile, 64x64 warps, async pipeline ----------------
// CTA: M=128 co x N=256 px (4 image rows). 8 warps (2x4), warp tile 64x64;
// warp's wn selects its image row. Accums 128 f32/thread, 1 CTA/SM.
// A: 2-stage cp.async (fragment-major). B: double-buffered 6-row tap-shift
// slab, cp.async-prefetched at tap==0 with 9 chunks of slack.
#define A_STAGE   16384
#define SLAB_P    424                  // floats per ci (6*68 + 16 pad); %32==8 -> conflict-free
#define SLAB_R    68                   // floats per image row (cols 0..3 pad, data 4..67)
#define SLAB_FLOATS (32 * SLAB_P)      // 13568
#define SLAB_BYTES (SLAB_FLOATS * 4)   // 54272
#define SMEM_BYTES (2 * A_STAGE + 2 * SLAB_BYTES)   // 141312 -> 1 CTA/SM

#define CP16_CG(dst, src) \
    asm volatile("cp.async.cg.shared.global [%0], [%1], 16;" :: "r"(dst), "l"(src))
#define CP_COMMIT()   asm volatile("cp.async.commit_group;" ::: "memory")
#define CP_WAIT_ALL() asm volatile("cp.async.wait_group 0;" ::: "memory")

#define MMA_TF32(c, a, b0, b1)                                                 \
    asm volatile("mma.sync.aligned.m16n8k8.row.col.f32.tf32.tf32.f32 "         \
        "{%0,%1,%2,%3}, {%4,%5,%6,%7}, {%8,%9}, {%0,%1,%2,%3};"                \
        : "+f"((c)[0]), "+f"((c)[1]), "+f"((c)[2]), "+f"((c)[3])               \
        : "r"((a).x), "r"((a).y), "r"((a).z), "r"((a).w), "r"(b0), "r"(b1))

__global__ void __launch_bounds__(256, 1)
conv_mma(const float* __restrict__ x, const float* __restrict__ noise,
         const float* __restrict__ bias, const float* __restrict__ nwptr,
         float* __restrict__ out) {
    extern __shared__ __align__(16) char smem[];
    float* slabs = (float*)(smem + 2 * A_STAGE);
    const uint32_t sbase = (uint32_t)__cvta_generic_to_shared(smem);

    const int tid  = threadIdx.x;
    const int w    = tid >> 5;
    const int lane = tid & 31;
    const int g    = lane >> 2;
    const int tig  = lane & 3;
    const int wm   = w >> 2;               // 0..1: 64-row m half
    const int wn   = w & 3;                // 0..3: image row within tile

    const int y0     = blockIdx.x * 4;     // 16 row-quads
    const int coBase = blockIdx.y * 128;
    const int b      = blockIdx.z;

    const float*  xb  = x + (size_t)b * (CIN * HH * WW);
    const float4* wa4 = (const float4*)g_wA + ((size_t)(b * 2 + blockIdx.y)) * (72 * 1024);

    // zero both slabs once (pads + out-of-range rows stay zero)
    for (int i = tid; i < 2 * SLAB_FLOATS / 4; i += 256)
        ((float4*)slabs)[i] = make_float4(0.f, 0.f, 0.f, 0.f);

    float c[4][8][4];
#pragma unroll
    for (int mt = 0; mt < 4; mt++)
#pragma unroll
        for (int nt = 0; nt < 8; nt++)
#pragma unroll
            for (int i = 0; i < 4; i++) c[mt][nt][i] = 0.f;

    auto load_A = [&](int chunk, int buf) {
        const uint32_t abase = sbase + buf * A_STAGE;
        const float4* src4 = wa4 + chunk * 1024;
#pragma unroll
        for (int i = 0; i < 4; i++) {
            int idx = tid + 256 * i;
            CP16_CG(abase + idx * 16, src4 + idx);
        }
    };
    // slab: 32 ci x 6 rows x 16 float4 = 3072 cp16 -> 12 per thread
    auto load_slab = [&](int cig, int sb) {
        const uint32_t slbase = sbase + 2 * A_STAGE + sb * SLAB_BYTES;
#pragma unroll
        for (int i = 0; i < 12; i++) {
            int o   = tid + i * 256;
            int row = o >> 4;              // 0..191 (ci,ry)
            int f   = o & 15;
            int ci  = row / 6;
            int ry  = row - ci * 6;
            int y   = y0 - 1 + ry;
            if ((unsigned)y < HH) {
                const float* src = xb + (size_t)(cig * 32 + ci) * (HH * WW) + y * WW + f * 4;
                CP16_CG(slbase + (ci * SLAB_P + ry * SLAB_R + 4 + f * 4) * 4, src);
            }
        }
    };

    __syncthreads();                       // zeroing visible before cp.async writes
    load_A(0, 0);
    load_slab(0, 0);
    CP_COMMIT();

    // B fragment base: ci-part tig*SLAB_P, row wn(+ky), col g(+3+kx), +nt*8
    const int bfrag0 = tig * SLAB_P + wn * SLAB_R + g + 3;

    for (int chunk = 0; chunk < 72; chunk++) {
        CP_WAIT_ALL();
        __syncthreads();

        const int cig = chunk / 9;
        const int tap = chunk - 9 * cig;

        if (chunk + 1 < 72) {
            load_A(chunk + 1, (chunk + 1) & 1);
            if (tap == 0 && cig + 1 < 8) load_slab(cig + 1, (cig + 1) & 1);
            CP_COMMIT();
        }

        const int ky = tap / 3;
        const int kx = tap - ky * 3;
        const float* bptr = slabs + (cig & 1) * SLAB_FLOATS + bfrag0 + ky * SLAB_R + kx;
        const uint4* Af = (const uint4*)(smem + (chunk & 1) * A_STAGE);

#pragma unroll
        for (int ks = 0; ks < 4; ks++) {
            uint4 a[4];
#pragma unroll
            for (int mt = 0; mt < 4; mt++)
                a[mt] = Af[((ks * 2 + wm) * 4 + mt) * 32 + lane];
            const float* bk = bptr + ks * (8 * SLAB_P);
#pragma unroll
            for (int nt = 0; nt < 8; nt++) {
                uint32_t b0 = __float_as_uint(bk[nt * 8]);
                uint32_t b1 = __float_as_uint(bk[nt * 8 + 4 * SLAB_P]);
#pragma unroll
                for (int mt = 0; mt < 4; mt++)
                    MMA_TF32(c[mt][nt], a[mt], b0, b1);
            }
        }
    }

    // ---- epilogue: noise + bias + leaky_relu * sqrt(2); warp wn owns row y0+wn
    {
        const float nw = nwptr[0];
        const int y = y0 + wn;
        const float* nzrow = noise + (size_t)b * (HH * WW) + y * WW;
#pragma unroll
        for (int mt = 0; mt < 4; mt++) {
            int co0 = coBase + wm * 64 + mt * 16 + g;
            float bv0 = bias[co0];
            float bv1 = bias[co0 + 8];
            float* o0 = out + (size_t)(b * COUT + co0) * (HH * WW) + y * WW;
            float* o1 = o0 + 8 * (HH * WW);
#pragma unroll
            for (int nt = 0; nt < 8; nt++) {
                int xc = nt * 8 + tig * 2;
                float2 nz = *(const float2*)(nzrow + xc);
                float nzx = nz.x * nw, nzy = nz.y * nw;
                float v0 = c[mt][nt][0] + nzx + bv0;
                float v1 = c[mt][nt][1] + nzy + bv0;
                float v2 = c[mt][nt][2] + nzx + bv1;
                float v3 = c[mt][nt][3] + nzy + bv1;
                v0 = (v0 > 0.f ? v0 : 0.2f * v0) * 1.41421356237309515f;
                v1 = (v1 > 0.f ? v1 : 0.2f * v1) * 1.41421356237309515f;
                v2 = (v2 > 0.f ? v2 : 0.2f * v2) * 1.41421356237309515f;
                v3 = (v3 > 0.f ? v3 : 0.2f * v3) * 1.41421356237309515f;
                *(float2*)(o0 + xc) = make_float2(v0, v1);
                *(float2*)(o1 + xc) = make_float2(v2, v3);
            }
        }
    }
}

// ---------------- launch ----------------
extern "C" void kernel_launch(void* const* d_in, const int* in_sizes, int n_in,
                              void* d_out, int out_size) {
    const float* x        = (const float*)d_in[0];
    const float* style    = (const float*)d_in[1];
    const float* noise    = (const float*)d_in[2];
    const float* weight   = (const float*)d_in[3];
    const float* style_w  = (const float*)d_in[4];
    const float* style_b  = (const float*)d_in[5];
    const float* bias     = (const float*)d_in[6];
    const float* nw       = (const float*)d_in[7];
    float* out = (float*)d_out;

    cudaFuncSetAttribute(conv_mma, cudaFuncAttributeMaxDynamicSharedMemorySize, SMEM_BYTES);

    fused1_kernel<<<272, 256>>>(style, style_w, style_b, weight);  // 1
    d_kernel<<<BATCH, 256>>>();                                    // 2
    wa_kernel<<<9216, 256>>>(weight);                              // 3
    conv_mma<<<dim3(16, 2, 16), 256, SMEM_BYTES>>>(x, noise, bias, nw, out);  // 4
}

// round 13
// speedup vs baseline: 1.0763x; 1.0763x over previous
#include <cuda_runtime.h>
#include <cstdint>

#define BATCH 16
#define CIN   256
#define COUT  256
#define HH    64
#define WW    64
#define LAT   512
#define KTOT  2304

// ---------------- scratch (device globals; no allocation) ----------------
__device__ __align__(16) float g_s[BATCH * CIN];
__device__ __align__(16) float g_d[BATCH * COUT];
__device__ __align__(16) float g_wss[CIN * COUT];
// A panels, fragment-major: [b][cot][chunk(72)][ks(4)][wm(2)][mt(4)][lane(32)] float4
__device__ __align__(16) float g_wA[(size_t)BATCH * 2 * KTOT * 128];

__device__ __forceinline__ uint32_t tf32_rna(float v) {
    uint32_t u;
    asm("cvt.rna.tf32.f32 %0, %1;" : "=r"(u) : "f"(v));
    return u;
}

// ---------------- prep kernels ----------------
__global__ void fused1_kernel(const float* __restrict__ style,
                              const float* __restrict__ style_w,
                              const float* __restrict__ style_b,
                              const float* __restrict__ weight) {
    if (blockIdx.x < 16) {
        __shared__ float st[LAT];
        int b = blockIdx.x, tid = threadIdx.x;
        st[tid]       = style[b * LAT + tid];
        st[tid + 256] = style[b * LAT + tid + 256];
        __syncthreads();
        float acc = style_b[tid];
#pragma unroll 8
        for (int l = 0; l < LAT; l++) acc += st[l] * style_w[l * CIN + tid];
        g_s[b * CIN + tid] = acc;
    } else {
        int ci = blockIdx.x - 16, co = threadIdx.x;
        const float* wp = weight + co * (CIN * 9) + ci * 9;
        float s = 0.f;
#pragma unroll
        for (int t = 0; t < 9; t++) { float v = wp[t]; s += v * v; }
        g_wss[ci * COUT + co] = s;
    }
}

__global__ void d_kernel() {
    __shared__ float s2[CIN];
    int b = blockIdx.x, co = threadIdx.x;
    float sv = g_s[b * CIN + co];
    s2[co] = sv * sv;
    __syncthreads();
    float acc = 1e-8f;
#pragma unroll 8
    for (int ci = 0; ci < CIN; ci++) acc += g_wss[ci * COUT + co] * s2[ci];
    g_d[b * COUT + co] = rsqrtf(acc);
}

// Fragment-major modulated weights (validated layout).
__global__ void wa_kernel(const float* __restrict__ weight) {
    int o = blockIdx.x * 256 + threadIdx.x;
    int lane = o & 31; int t = o >> 5;
    int mt = t & 3;  t >>= 2;
    int wm = t & 1;  t >>= 1;
    int ks = t & 3;  t >>= 2;
    int chunk = t % 72; t /= 72;
    int cot = t & 1; int b = t >> 1;
    int g = lane >> 2, tig = lane & 3;
    int kk  = ks * 8 + tig;
    int cig = chunk / 9, tap = chunk - 9 * cig;
    int ci  = cig * 32 + kk;
    int co  = cot * 128 + wm * 64 + mt * 16 + g;
    float s0 = g_s[b * CIN + ci],  s1 = g_s[b * CIN + ci + 4];
    float d0 = g_d[b * COUT + co], d1 = g_d[b * COUT + co + 8];
    float4 r;
    r.x = __uint_as_float(tf32_rna(weight[(co * CIN + ci) * 9 + tap]           * s0 * d0));
    r.y = __uint_as_float(tf32_rna(weight[((co + 8) * CIN + ci) * 9 + tap]     * s0 * d1));
    r.z = __uint_as_float(tf32_rna(weight[(co * CIN + ci + 4) * 9 + tap]       * s1 * d0));
    r.w = __uint_as_float(tf32_rna(weight[((co + 8) * CIN + ci + 4) * 9 + tap] * s1 * d1));
    ((float4*)g_wA)[o] = r;
}

// ---------------- main: R8 config + smoothed slab prefetch ----------------
// CTA: M=128 co x N=128 px (2 rows). 8 warps (2x4), warp tile 64x32, 2 CTA/SM.
// A: 2-stage cp.async. B: double-buffered tap-shift slab; the NEXT ci-group's
// slab is prefetched in 8 pieces, one per chunk at taps 0..7 (1 cp16/thread),
// so LSU issue is flat and every piece has >=1 full chunk of latency slack.
#define A_STAGE   16384
#define SLAB_P    296                  // floats per ci (4*68 + 24 pad); %32==8 -> conflict-free
#define SLAB_R    68                   // floats per image row (cols 0..3 pad, data 4..67)
#define SLAB_FLOATS (32 * SLAB_P)      // 9472
#define SLAB_BYTES (SLAB_FLOATS * 4)   // 37888
#define SMEM_BYTES (2 * A_STAGE + 2 * SLAB_BYTES)   // 108544 -> 2 CTAs/SM

#define CP16_CG(dst, src) \
    asm volatile("cp.async.cg.shared.global [%0], [%1], 16;" :: "r"(dst), "l"(src))
#define CP_COMMIT()   asm volatile("cp.async.commit_group;" ::: "memory")
#define CP_WAIT_ALL() asm volatile("cp.async.wait_group 0;" ::: "memory")

#define MMA_TF32(c, a, b0, b1)                                                 \
    asm volatile("mma.sync.aligned.m16n8k8.row.col.f32.tf32.tf32.f32 "         \
        "{%0,%1,%2,%3}, {%4,%5,%6,%7}, {%8,%9}, {%0,%1,%2,%3};"                \
        : "+f"((c)[0]), "+f"((c)[1]), "+f"((c)[2]), "+f"((c)[3])               \
        : "r"((a).x), "r"((a).y), "r"((a).z), "r"((a).w), "r"(b0), "r"(b1))

__global__ void __launch_bounds__(256, 2)
conv_mma(const float* __restrict__ x, const float* __restrict__ noise,
         const float* __restrict__ bias, const float* __restrict__ nwptr,
         float* __restrict__ out) {
    extern __shared__ __align__(16) char smem[];
    float* slabs = (float*)(smem + 2 * A_STAGE);
    const uint32_t sbase = (uint32_t)__cvta_generic_to_shared(smem);

    const int tid  = threadIdx.x;
    const int w    = tid >> 5;
    const int lane = tid & 31;
    const int g    = lane >> 2;
    const int tig  = lane & 3;
    const int wm   = w >> 2;
    const int wn   = w & 3;

    const int y0     = blockIdx.x * 2;
    const int coBase = blockIdx.y * 128;
    const int b      = blockIdx.z;

    const float*  xb  = x + (size_t)b * (CIN * HH * WW);
    const float4* wa4 = (const float4*)g_wA + ((size_t)(b * 2 + blockIdx.y)) * (72 * 1024);

    // zero both slabs once (pads + out-of-range rows stay zero forever)
    for (int i = tid; i < 2 * SLAB_FLOATS / 4; i += 256)
        ((float4*)slabs)[i] = make_float4(0.f, 0.f, 0.f, 0.f);

    float c[4][4][4];
#pragma unroll
    for (int mt = 0; mt < 4; mt++)
#pragma unroll
        for (int nt = 0; nt < 4; nt++)
#pragma unroll
            for (int i = 0; i < 4; i++) c[mt][nt][i] = 0.f;

    auto load_A = [&](int chunk, int buf) {
        const uint32_t abase = sbase + buf * A_STAGE;
        const float4* src4 = wa4 + chunk * 1024;
#pragma unroll
        for (int i = 0; i < 4; i++) {
            int idx = tid + 256 * i;
            CP16_CG(abase + idx * 16, src4 + idx);
        }
    };
    // one slab piece: 256 float4 of the 2048 total (rows 0..127 x 16 float4)
    auto load_slab_piece = [&](int cig, int sb, int piece) {
        const uint32_t slbase = sbase + 2 * A_STAGE + sb * SLAB_BYTES;
        int o   = piece * 256 + tid;
        int row = o >> 4;              // (ci,ry) pair 0..127
        int f   = o & 15;
        int ci  = row >> 2;
        int ry  = row & 3;
        int y   = y0 - 1 + ry;
        if ((unsigned)y < HH) {
            const float* src = xb + (size_t)(cig * 32 + ci) * (HH * WW) + y * WW + f * 4;
            CP16_CG(slbase + (ci * SLAB_P + ry * SLAB_R + 4 + f * 4) * 4, src);
        }
    };

    __syncthreads();                       // zeroing visible before cp.async writes
    load_A(0, 0);
#pragma unroll
    for (int p = 0; p < 8; p++) load_slab_piece(0, 0, p);
    CP_COMMIT();

    // per-thread B fragment base (excl. ks/tap terms); data col = 4 + xx
    const int bfrag0 = tig * SLAB_P + (wn >> 1) * SLAB_R + (wn & 1) * 32 + g + 3;

    for (int chunk = 0; chunk < 72; chunk++) {
        CP_WAIT_ALL();
        __syncthreads();

        const int cig = chunk / 9;
        const int tap = chunk - 9 * cig;

        if (chunk + 1 < 72) {
            load_A(chunk + 1, (chunk + 1) & 1);
            if (tap < 8 && cig + 1 < 8) load_slab_piece(cig + 1, (cig + 1) & 1, tap);
            CP_COMMIT();
        }

        const int ky = tap / 3;
        const int kx = tap - ky * 3;
        const float* bptr = slabs + (cig & 1) * SLAB_FLOATS + bfrag0 + ky * SLAB_R + kx;
        const uint4* Af = (const uint4*)(smem + (chunk & 1) * A_STAGE);

#pragma unroll
        for (int ks = 0; ks < 4; ks++) {
            uint4 a[4];
#pragma unroll
            for (int mt = 0; mt < 4; mt++)
                a[mt] = Af[((ks * 2 + wm) * 4 + mt) * 32 + lane];
            const float* bk = bptr + ks * (8 * SLAB_P);
            uint32_t b0[4], b1[4];
#pragma unroll
            for (int nt = 0; nt < 4; nt++) {
                b0[nt] = __float_as_uint(bk[nt * 8]);
                b1[nt] = __float_as_uint(bk[nt * 8 + 4 * SLAB_P]);
            }
#pragma unroll
            for (int mt = 0; mt < 4; mt++)
#pragma unroll
                for (int nt = 0; nt < 4; nt++)
                    MMA_TF32(c[mt][nt], a[mt], b0[nt], b1[nt]);
        }
    }

    // ---- epilogue: noise + bias + leaky_relu * sqrt(2)
    {
        const float nw = nwptr[0];
        const int y = y0 + (wn >> 1);
        const float* nzrow = noise + (size_t)b * (HH * WW) + y * WW;
#pragma unroll
        for (int mt = 0; mt < 4; mt++) {
            int co0 = coBase + wm * 64 + mt * 16 + g;
            float bv0 = bias[co0];
            float bv1 = bias[co0 + 8];
            float* o0 = out + (size_t)(b * COUT + co0) * (HH * WW) + y * WW;
            float* o1 = o0 + 8 * (HH * WW);
#pragma unroll
            for (int nt = 0; nt < 4; nt++) {
                int xc = (wn & 1) * 32 + nt * 8 + tig * 2;
                float2 nz = *(const float2*)(nzrow + xc);
                float nzx = nz.x * nw, nzy = nz.y * nw;
                float v0 = c[mt][nt][0] + nzx + bv0;
                float v1 = c[mt][nt][1] + nzy + bv0;
                float v2 = c[mt][nt][2] + nzx + bv1;
                float v3 = c[mt][nt][3] + nzy + bv1;
                v0 = (v0 > 0.f ? v0 : 0.2f * v0) * 1.41421356237309515f;
                v1 = (v1 > 0.f ? v1 : 0.2f * v1) * 1.41421356237309515f;
                v2 = (v2 > 0.f ? v2 : 0.2f * v2) * 1.41421356237309515f;
                v3 = (v3 > 0.f ? v3 : 0.2f * v3) * 1.41421356237309515f;
                *(float2*)(o0 + xc) = make_float2(v0, v1);
                *(float2*)(o1 + xc) = make_float2(v2, v3);
            }
        }
    }
}

// ---------------- launch ----------------
extern "C" void kernel_launch(void* const* d_in, const int* in_sizes, int n_in,
                              void* d_out, int out_size) {
    const float* x        = (const float*)d_in[0];
    const float* style    = (const float*)d_in[1];
    const float* noise    = (const float*)d_in[2];
    const float* weight   = (const float*)d_in[3];
    const float* style_w  = (const float*)d_in[4];
    const float* style_b  = (const float*)d_in[5];
    const float* bias     = (const float*)d_in[6];
    const float* nw       = (const float*)d_in[7];
    float* out = (float*)d_out;

    cudaFuncSetAttribute(conv_mma, cudaFuncAttributeMaxDynamicSharedMemorySize, SMEM_BYTES);

    fused1_kernel<<<272, 256>>>(style, style_w, style_b, weight);  // 1
    d_kernel<<<BATCH, 256>>>();                                    // 2
    wa_kernel<<<9216, 256>>>(weight);                              // 3
    conv_mma<<<dim3(32, 2, 16), 256, SMEM_BYTES>>>(x, noise, bias, nw, out);  // 4
}